// round 5
// baseline (speedup 1.0000x reference)
#include <cuda_runtime.h>
#include <cuda_fp16.h>

#define D 16
#define GBLK 64

// Scratch (allocation-free rule: __device__ globals). uint4-typed for 16B alignment.
__device__ float g_MW[4096];              // MW[j][k][l] = sum_n Wc1[j,n] * M[n,k,l]
__device__ float g_bb[16];                // bb[j] = bc1[j] + sum_n Wc1[j,n]*Boff[n]
__device__ float g_E3f[20000 * 16];       // fp32 MLP output per gene (input to k_uw)
__device__ uint4 g_E3h[20000 * 2];        // fp16 MLP output per gene (input to k_main)
__device__ uint4 g_UWh[20000 * 32];       // fp16: uint2 at [g*64 + c*16 + j] = UW[g][j][4c..4c+3]

// ---------------------------------------------------------------------------
// Kernel 1 (fused): blocks 0..15 compute MW[j]+bb; blocks 16.. run gene MLP.
//   MW[j,k,l] = sum_{n,m} Wc1[j,n]*BD[n,m]*BW[n,m,k]*BW[m,n,l]
//   E3[g]     = W3*relu(W2*relu(W1*emb[g]+b1)+b2)+b3
// The two halves are independent -> MW rides free under the E3 wave.
// ---------------------------------------------------------------------------
__global__ void k_pre(const float* __restrict__ BW, const float* __restrict__ BD,
                      const float* __restrict__ Wc1, const float* __restrict__ bc1,
                      const float* __restrict__ Boff,
                      const float* __restrict__ emb,
                      const float* __restrict__ W1, const float* __restrict__ b1,
                      const float* __restrict__ W2, const float* __restrict__ b2,
                      const float* __restrict__ W3, const float* __restrict__ b3,
                      int genes) {
    int t = threadIdx.x;

    if (blockIdx.x < 16) {
        // ---- MW block: stage all operands in shared (one coalesced burst) ----
        __shared__ float sBW[4096], sBD[256], sWc1[256];
        {
            const float4* s = (const float4*)BW;
            float4* d = (float4*)sBW;
#pragma unroll
            for (int q = 0; q < 4; q++) d[t + 256 * q] = s[t + 256 * q];
            if (t < 64)       ((float4*)sBD)[t]       = ((const float4*)BD)[t];
            else if (t < 128) ((float4*)sWc1)[t - 64] = ((const float4*)Wc1)[t - 64];
        }
        __syncthreads();

        int j = blockIdx.x;
        int k = t >> 4, l = t & 15;
        float s = 0.f;
#pragma unroll
        for (int n = 0; n < 16; n++) {
            float wjn = sWc1[j * 16 + n];
#pragma unroll
            for (int m = 0; m < 16; m++) {
                float p = wjn * sBD[n * 16 + m];
                s = fmaf(p * sBW[n * 256 + m * 16 + k], sBW[m * 256 + n * 16 + l], s);
            }
        }
        g_MW[j * 256 + t] = s;

        if (blockIdx.x == 0 && t < 16) {
            float b = bc1[t];
#pragma unroll
            for (int n = 0; n < 16; n++) b = fmaf(sWc1[t * 16 + n], Boff[n], b);
            g_bb[t] = b;
        }
        return;
    }

    // ---- E3 blocks: 64 genes per block, 16 lanes/gene, weights in registers ----
    int lane = t & 15;
    int base = (blockIdx.x - 16) * GBLK;

    float w1r[16], w2r[16], w3r[16];
    {
        const float4* r1 = (const float4*)(W1 + lane * 16);
        const float4* r2 = (const float4*)(W2 + lane * 16);
        const float4* r3 = (const float4*)(W3 + lane * 16);
#pragma unroll
        for (int q = 0; q < 4; q++) {
            float4 a = r1[q]; w1r[q*4+0]=a.x; w1r[q*4+1]=a.y; w1r[q*4+2]=a.z; w1r[q*4+3]=a.w;
            float4 b = r2[q]; w2r[q*4+0]=b.x; w2r[q*4+1]=b.y; w2r[q*4+2]=b.z; w2r[q*4+3]=b.w;
            float4 c = r3[q]; w3r[q*4+0]=c.x; w3r[q*4+1]=c.y; w3r[q*4+2]=c.z; w3r[q*4+3]=c.w;
        }
    }
    float bias1 = b1[lane], bias2 = b2[lane], bias3 = b3[lane];

#pragma unroll
    for (int it = 0; it < 4; it++) {
        int glocal = (t >> 4) + 16 * it;
        int g = base + glocal;
        int gc = (g < genes) ? g : (genes - 1);
        float v = emb[(size_t)gc * 16 + lane];

        float h = bias1;
#pragma unroll
        for (int jj = 0; jj < 16; jj++)
            h = fmaf(w1r[jj], __shfl_sync(0xffffffffu, v, jj, 16), h);
        v = fmaxf(h, 0.f);
        h = bias2;
#pragma unroll
        for (int jj = 0; jj < 16; jj++)
            h = fmaf(w2r[jj], __shfl_sync(0xffffffffu, v, jj, 16), h);
        v = fmaxf(h, 0.f);
        h = bias3;
#pragma unroll
        for (int jj = 0; jj < 16; jj++)
            h = fmaf(w3r[jj], __shfl_sync(0xffffffffu, v, jj, 16), h);

        if (g < genes) {
            g_E3f[(size_t)g * 16 + lane] = h;
            ((__half*)g_E3h)[(size_t)g * 16 + lane] = __float2half_rn(h);
        }
    }
}

// ---------------------------------------------------------------------------
// Kernel 2: UW[g,j,k] = sum_l MW[j,k,l]*E3[g,l], fp16 output.
// 64 genes/block. E3 staged shared (coalesced float4); thread owns (j, kchunk)
// with its 64 MW weights in registers; streams 16 genes; 1 STG.64 per gene.
// ---------------------------------------------------------------------------
__global__ void k_uw(int genes) {
    __shared__ float sv[GBLK * 17];
    int t = threadIdx.x;
    int base = blockIdx.x * GBLK;

    // stage 64 genes x 16 floats: one float4 per thread
    {
        int fidx = base * 4 + t;             // global float4 index
        int gl = t >> 2, q = t & 3;
        float4 v = make_float4(0.f, 0.f, 0.f, 0.f);
        if (fidx < genes * 4) v = ((const float4*)g_E3f)[fidx];
        sv[gl * 17 + q * 4 + 0] = v.x;
        sv[gl * 17 + q * 4 + 1] = v.y;
        sv[gl * 17 + q * 4 + 2] = v.z;
        sv[gl * 17 + q * 4 + 3] = v.w;
    }

    int j = t & 15;
    int c = (t >> 4) & 3;
    int sg = t >> 6;

    float mw[64];
    {
        const float4* mp = (const float4*)(g_MW + j * 256 + c * 64);
#pragma unroll
        for (int q = 0; q < 16; q++) {
            float4 m4 = mp[q];
            mw[q*4+0]=m4.x; mw[q*4+1]=m4.y; mw[q*4+2]=m4.z; mw[q*4+3]=m4.w;
        }
    }
    __syncthreads();

    uint2* outp = (uint2*)g_UWh;
#pragma unroll
    for (int gi = 0; gi < 16; gi++) {
        int gl = gi * 4 + sg;
        int g = base + gl;
        float u0 = 0.f, u1 = 0.f, u2 = 0.f, u3 = 0.f;
#pragma unroll
        for (int l = 0; l < 16; l++) {
            float ev = sv[gl * 17 + l];
            u0 = fmaf(mw[0  + l], ev, u0);
            u1 = fmaf(mw[16 + l], ev, u1);
            u2 = fmaf(mw[32 + l], ev, u2);
            u3 = fmaf(mw[48 + l], ev, u3);
        }
        if (g < genes) {
            __half2 h01 = __floats2half2_rn(u0, u1);
            __half2 h23 = __floats2half2_rn(u2, u3);
            uint2 v;
            v.x = *(unsigned*)&h01;
            v.y = *(unsigned*)&h23;
            outp[(size_t)g * 64 + c * 16 + j] = v;
        }
    }
}

// ---------------------------------------------------------------------------
// Kernel 3: main. 16 lanes/row (2 rows/warp), lane j owns classifier unit j.
//   y_j = relu(E3h[x0] . UWh[x1,j,:] + bb[j]);  out = sum_j Wc2[j]*y_j + bc2 + sum(phenos)
// fp16 table loads, fp32 math. L2-bandwidth-bound (~140MB gather).
// ---------------------------------------------------------------------------
__global__ void k_main(const int* __restrict__ x, const float* __restrict__ phenos,
                       const float* __restrict__ Wc2, const float* __restrict__ bc2,
                       float* __restrict__ out) {
    int t = threadIdx.x;
    int j = t & 15;
    int row = blockIdx.x * 16 + (t >> 4);

    int2 xi = ((const int2*)x)[row];
    const uint4* E = g_E3h + (size_t)xi.x * 2;
    uint4 e0 = E[0], e1 = E[1];
    const uint2* U = (const uint2*)(g_UWh + (size_t)xi.y * 32);
    uint2 q0 = U[j], q1 = U[16 + j], q2 = U[32 + j], q3 = U[48 + j];

    float z = g_bb[j];
    {
        unsigned ue[8] = {e0.x, e0.y, e0.z, e0.w, e1.x, e1.y, e1.z, e1.w};
        unsigned uu[8] = {q0.x, q0.y, q1.x, q1.y, q2.x, q2.y, q3.x, q3.y};
#pragma unroll
        for (int q = 0; q < 8; q++) {
            float2 a = __half22float2(*(__half2*)&ue[q]);
            float2 u = __half22float2(*(__half2*)&uu[q]);
            z = fmaf(a.x, u.x, z);
            z = fmaf(a.y, u.y, z);
        }
    }

    float acc = fmaxf(z, 0.f) * Wc2[j];
    acc += __shfl_xor_sync(0xffffffffu, acc, 8);
    acc += __shfl_xor_sync(0xffffffffu, acc, 4);
    acc += __shfl_xor_sync(0xffffffffu, acc, 2);
    acc += __shfl_xor_sync(0xffffffffu, acc, 1);

    if (j == 0) {
        float2 ph = ((const float2*)phenos)[row];
        out[row] = acc + bc2[0] + ph.x + ph.y;
    }
}

// ---------------------------------------------------------------------------
extern "C" void kernel_launch(void* const* d_in, const int* in_sizes, int n_in,
                              void* d_out, int out_size) {
    const int*   x      = (const int*)d_in[0];
    const float* phenos = (const float*)d_in[1];
    const float* emb    = (const float*)d_in[2];
    const float* W1 = (const float*)d_in[3],  *b1 = (const float*)d_in[4];
    const float* W2 = (const float*)d_in[5],  *b2 = (const float*)d_in[6];
    const float* W3 = (const float*)d_in[7],  *b3 = (const float*)d_in[8];
    const float* BW = (const float*)d_in[9],  *BD = (const float*)d_in[10];
    const float* Boff = (const float*)d_in[11];
    const float* Wc1 = (const float*)d_in[12], *bc1 = (const float*)d_in[13];
    const float* Wc2 = (const float*)d_in[14], *bc2 = (const float*)d_in[15];
    float* out = (float*)d_out;

    int rows  = in_sizes[0] / 2;     // 262144
    int genes = in_sizes[2] / D;     // 20000

    int eblocks = (genes + GBLK - 1) / GBLK;          // 313
    k_pre<<<16 + eblocks, 256>>>(BW, BD, Wc1, bc1, Boff, emb,
                                 W1, b1, W2, b2, W3, b3, genes);
    k_uw<<<eblocks, 256>>>(genes);
    k_main<<<rows / 16, 256>>>(x, phenos, Wc2, bc2, out);
}

// round 6
// speedup vs baseline: 1.1566x; 1.1566x over previous
#include <cuda_runtime.h>
#include <cuda_fp16.h>

#define D 16
#define GBLK 64

// Scratch (allocation-free rule: __device__ globals). uint4-typed for 16B alignment.
__device__ float g_MW[4096];              // MW[j][k][l] = sum_n Wc1[j,n] * M[n,k,l]
__device__ float g_bb[16];                // bb[j] = bc1[j] + sum_n Wc1[j,n]*Boff[n]
__device__ float g_E3f[20000 * 16];       // fp32 MLP output per gene (input to k_uw)
__device__ uint4 g_E3h[20000 * 2];        // fp16 MLP output per gene (input to k_main)
__device__ uint4 g_UWh[20000 * 32];       // fp16: uint2 at [g*64 + c*16 + j] = UW[g][j][4c..4c+3]

// ---------------------------------------------------------------------------
// Kernel 1 (fused): blocks 0..15 compute MW[j]+bb; blocks 16.. run gene MLP
// with ONE THREAD PER GENE (no shuffles, 16-way ILP per layer).
// ---------------------------------------------------------------------------
__global__ void k_pre(const float* __restrict__ BW, const float* __restrict__ BD,
                      const float* __restrict__ Wc1, const float* __restrict__ bc1,
                      const float* __restrict__ Boff,
                      const float* __restrict__ emb,
                      const float* __restrict__ W1, const float* __restrict__ b1,
                      const float* __restrict__ W2, const float* __restrict__ b2,
                      const float* __restrict__ W3, const float* __restrict__ b3,
                      int genes) {
    int t = threadIdx.x;

    if (blockIdx.x < 16) {
        // ---- MW block: stage operands in shared (one coalesced burst) ----
        __shared__ float sBW[4096], sBD[256], sWc1[256];
        {
            const float4* s = (const float4*)BW;
            float4* d = (float4*)sBW;
#pragma unroll
            for (int q = 0; q < 4; q++) d[t + 256 * q] = s[t + 256 * q];
            if (t < 64)       ((float4*)sBD)[t]       = ((const float4*)BD)[t];
            else if (t < 128) ((float4*)sWc1)[t - 64] = ((const float4*)Wc1)[t - 64];
        }
        __syncthreads();

        int j = blockIdx.x;
        int k = t >> 4, l = t & 15;
        float s = 0.f;
#pragma unroll
        for (int n = 0; n < 16; n++) {
            float wjn = sWc1[j * 16 + n];
#pragma unroll
            for (int m = 0; m < 16; m++) {
                float p = wjn * sBD[n * 16 + m];
                s = fmaf(p * sBW[n * 256 + m * 16 + k], sBW[m * 256 + n * 16 + l], s);
            }
        }
        g_MW[j * 256 + t] = s;

        if (blockIdx.x == 0 && t < 16) {
            float b = bc1[t];
#pragma unroll
            for (int n = 0; n < 16; n++) b = fmaf(sWc1[t * 16 + n], Boff[n], b);
            g_bb[t] = b;
        }
        return;
    }

    // ---- E3 blocks: one gene per thread, weights in shared ----
    __shared__ float sW1[256], sW2[256], sW3[256], sb[48];
    if (t < 64)        ((float4*)sW1)[t]       = ((const float4*)W1)[t];
    else if (t < 128)  ((float4*)sW2)[t - 64]  = ((const float4*)W2)[t - 64];
    else if (t < 192)  ((float4*)sW3)[t - 128] = ((const float4*)W3)[t - 128];
    else if (t < 208) { int i = t - 192; sb[i] = b1[i]; sb[16 + i] = b2[i]; sb[32 + i] = b3[i]; }
    __syncthreads();

    int g = (blockIdx.x - 16) * 256 + t;
    if (g >= genes) return;

    float v[16], h[16], o[16];
    {
        const float4* ep = (const float4*)(emb + (size_t)g * 16);
        float4 a = ep[0], b = ep[1], c = ep[2], dd = ep[3];
        v[0]=a.x; v[1]=a.y; v[2]=a.z; v[3]=a.w;
        v[4]=b.x; v[5]=b.y; v[6]=b.z; v[7]=b.w;
        v[8]=c.x; v[9]=c.y; v[10]=c.z; v[11]=c.w;
        v[12]=dd.x; v[13]=dd.y; v[14]=dd.z; v[15]=dd.w;
    }
#pragma unroll
    for (int i = 0; i < 16; i++) {
        float s = sb[i];
#pragma unroll
        for (int jj = 0; jj < 16; jj++) s = fmaf(sW1[i * 16 + jj], v[jj], s);
        h[i] = fmaxf(s, 0.f);
    }
#pragma unroll
    for (int i = 0; i < 16; i++) {
        float s = sb[16 + i];
#pragma unroll
        for (int jj = 0; jj < 16; jj++) s = fmaf(sW2[i * 16 + jj], h[jj], s);
        o[i] = fmaxf(s, 0.f);
    }
#pragma unroll
    for (int i = 0; i < 16; i++) {
        float s = sb[32 + i];
#pragma unroll
        for (int jj = 0; jj < 16; jj++) s = fmaf(sW3[i * 16 + jj], o[jj], s);
        v[i] = s;   // no relu on layer 3
    }

    float4* fp = (float4*)(g_E3f + (size_t)g * 16);
    fp[0] = make_float4(v[0], v[1], v[2], v[3]);
    fp[1] = make_float4(v[4], v[5], v[6], v[7]);
    fp[2] = make_float4(v[8], v[9], v[10], v[11]);
    fp[3] = make_float4(v[12], v[13], v[14], v[15]);

    uint4 hv[2];
    unsigned* hw = (unsigned*)hv;
#pragma unroll
    for (int q = 0; q < 8; q++) {
        __half2 p = __floats2half2_rn(v[2 * q], v[2 * q + 1]);
        hw[q] = *(unsigned*)&p;
    }
    g_E3h[(size_t)g * 2 + 0] = hv[0];
    g_E3h[(size_t)g * 2 + 1] = hv[1];
}

// ---------------------------------------------------------------------------
// Kernel 2: UW[g,j,k] = sum_l MW[j,k,l]*E3[g,l], fp16 output.
// 64 genes/block; thread owns (j, kchunk) with 64 MW weights in registers.
// ---------------------------------------------------------------------------
__global__ void k_uw(int genes) {
    __shared__ float sv[GBLK * 17];
    int t = threadIdx.x;
    int base = blockIdx.x * GBLK;

    {
        int fidx = base * 4 + t;
        int gl = t >> 2, q = t & 3;
        float4 v = make_float4(0.f, 0.f, 0.f, 0.f);
        if (fidx < genes * 4) v = ((const float4*)g_E3f)[fidx];
        sv[gl * 17 + q * 4 + 0] = v.x;
        sv[gl * 17 + q * 4 + 1] = v.y;
        sv[gl * 17 + q * 4 + 2] = v.z;
        sv[gl * 17 + q * 4 + 3] = v.w;
    }

    int j = t & 15;
    int c = (t >> 4) & 3;
    int sg = t >> 6;

    float mw[64];
    {
        const float4* mp = (const float4*)(g_MW + j * 256 + c * 64);
#pragma unroll
        for (int q = 0; q < 16; q++) {
            float4 m4 = mp[q];
            mw[q*4+0]=m4.x; mw[q*4+1]=m4.y; mw[q*4+2]=m4.z; mw[q*4+3]=m4.w;
        }
    }
    __syncthreads();

    uint2* outp = (uint2*)g_UWh;
#pragma unroll
    for (int gi = 0; gi < 16; gi++) {
        int gl = gi * 4 + sg;
        int g = base + gl;
        float u0 = 0.f, u1 = 0.f, u2 = 0.f, u3 = 0.f;
#pragma unroll
        for (int l = 0; l < 16; l++) {
            float ev = sv[gl * 17 + l];
            u0 = fmaf(mw[0  + l], ev, u0);
            u1 = fmaf(mw[16 + l], ev, u1);
            u2 = fmaf(mw[32 + l], ev, u2);
            u3 = fmaf(mw[48 + l], ev, u3);
        }
        if (g < genes) {
            __half2 h01 = __floats2half2_rn(u0, u1);
            __half2 h23 = __floats2half2_rn(u2, u3);
            uint2 v;
            v.x = *(unsigned*)&h01;
            v.y = *(unsigned*)&h23;
            outp[(size_t)g * 64 + c * 16 + j] = v;
        }
    }
}

// ---------------------------------------------------------------------------
// Kernel 3: main. 2 rows per 16-lane group (4 rows/warp) for doubled MLP.
// ---------------------------------------------------------------------------
__global__ void k_main(const int* __restrict__ x, const float* __restrict__ phenos,
                       const float* __restrict__ Wc2, const float* __restrict__ bc2,
                       float* __restrict__ out) {
    int t = threadIdx.x;
    int j = t & 15;
    int grp = t >> 4;                      // 0..15
    int row0 = blockIdx.x * 32 + grp;
    int row1 = row0 + 16;

    int2 xa = ((const int2*)x)[row0];
    int2 xb = ((const int2*)x)[row1];

    const uint4* Ea = g_E3h + (size_t)xa.x * 2;
    const uint4* Eb = g_E3h + (size_t)xb.x * 2;
    uint4 ea0 = Ea[0], ea1 = Ea[1];
    uint4 eb0 = Eb[0], eb1 = Eb[1];
    const uint2* Ua = (const uint2*)(g_UWh + (size_t)xa.y * 32);
    const uint2* Ub = (const uint2*)(g_UWh + (size_t)xb.y * 32);
    uint2 qa0 = Ua[j], qa1 = Ua[16 + j], qa2 = Ua[32 + j], qa3 = Ua[48 + j];
    uint2 qb0 = Ub[j], qb1 = Ub[16 + j], qb2 = Ub[32 + j], qb3 = Ub[48 + j];

    float bbj = g_bb[j];
    float z0 = bbj, z1 = bbj;
    {
        unsigned uea[8] = {ea0.x, ea0.y, ea0.z, ea0.w, ea1.x, ea1.y, ea1.z, ea1.w};
        unsigned uua[8] = {qa0.x, qa0.y, qa1.x, qa1.y, qa2.x, qa2.y, qa3.x, qa3.y};
        unsigned ueb[8] = {eb0.x, eb0.y, eb0.z, eb0.w, eb1.x, eb1.y, eb1.z, eb1.w};
        unsigned uub[8] = {qb0.x, qb0.y, qb1.x, qb1.y, qb2.x, qb2.y, qb3.x, qb3.y};
#pragma unroll
        for (int q = 0; q < 8; q++) {
            float2 a = __half22float2(*(__half2*)&uea[q]);
            float2 u = __half22float2(*(__half2*)&uua[q]);
            z0 = fmaf(a.x, u.x, z0);
            z0 = fmaf(a.y, u.y, z0);
            float2 b = __half22float2(*(__half2*)&ueb[q]);
            float2 w = __half22float2(*(__half2*)&uub[q]);
            z1 = fmaf(b.x, w.x, z1);
            z1 = fmaf(b.y, w.y, z1);
        }
    }

    float wc = Wc2[j];
    float acc0 = fmaxf(z0, 0.f) * wc;
    float acc1 = fmaxf(z1, 0.f) * wc;
#pragma unroll
    for (int m = 8; m >= 1; m >>= 1) {
        acc0 += __shfl_xor_sync(0xffffffffu, acc0, m);
        acc1 += __shfl_xor_sync(0xffffffffu, acc1, m);
    }

    if (j == 0) {
        float bc = bc2[0];
        float2 p0 = ((const float2*)phenos)[row0];
        float2 p1 = ((const float2*)phenos)[row1];
        out[row0] = acc0 + bc + p0.x + p0.y;
        out[row1] = acc1 + bc + p1.x + p1.y;
    }
}

// ---------------------------------------------------------------------------
extern "C" void kernel_launch(void* const* d_in, const int* in_sizes, int n_in,
                              void* d_out, int out_size) {
    const int*   x      = (const int*)d_in[0];
    const float* phenos = (const float*)d_in[1];
    const float* emb    = (const float*)d_in[2];
    const float* W1 = (const float*)d_in[3],  *b1 = (const float*)d_in[4];
    const float* W2 = (const float*)d_in[5],  *b2 = (const float*)d_in[6];
    const float* W3 = (const float*)d_in[7],  *b3 = (const float*)d_in[8];
    const float* BW = (const float*)d_in[9],  *BD = (const float*)d_in[10];
    const float* Boff = (const float*)d_in[11];
    const float* Wc1 = (const float*)d_in[12], *bc1 = (const float*)d_in[13];
    const float* Wc2 = (const float*)d_in[14], *bc2 = (const float*)d_in[15];
    float* out = (float*)d_out;

    int rows  = in_sizes[0] / 2;     // 262144
    int genes = in_sizes[2] / D;     // 20000

    int eblocks = (genes + 255) / 256;                // 79
    k_pre<<<16 + eblocks, 256>>>(BW, BD, Wc1, bc1, Boff, emb,
                                 W1, b1, W2, b2, W3, b3, genes);
    k_uw<<<(genes + GBLK - 1) / GBLK, 256>>>(genes);
    k_main<<<rows / 32, 256>>>(x, phenos, Wc2, bc2, out);
}